// round 2
// baseline (speedup 1.0000x reference)
#include <cuda_runtime.h>
#include <cstdint>

#define NT 128

// packed symmetric index for 13x13 (upper triangle)
__device__ __forceinline__ int sidx(int r, int c) {
    int lo = r < c ? r : c;
    int hi = r < c ? c : r;
    return lo * 13 - (lo * (lo - 1)) / 2 + (hi - lo);
}

#define MM(r, c) sm[sidx((r), (c)) * NT + tid]

__global__ void __launch_bounds__(NT)
mtm_refine_kernel(const float* __restrict__ Min, const float* __restrict__ Tin,
                  float* __restrict__ outT, float* __restrict__ outOm, int N)
{
    __shared__ float sm[91 * NT];   // 46592 B: symmetric-packed MtM per thread, [elem][lane]
    const int tid  = threadIdx.x;
    const int base = blockIdx.x * NT;

    // ---- cooperative, coalesced load of MtM into packed-symmetric SMEM ----
    {
        int np = N - base; if (np > NT) np = NT;
        const float* g = Min + (size_t)base * 169;
        const int limit = np * 169;
        for (int idx = tid; idx < limit; idx += NT) {
            int p = idx / 169;
            int e = idx - p * 169;
            int r = e / 13;
            int c = e - r * 13;
            float v = g[idx];
            if (r <= c) sm[sidx(r, c) * NT + p] = v;
        }
    }
    __syncthreads();

    const int gp = base + tid;
    if (gp >= N) return;

    // ---- load T (4x4) ----
    float Tm[16];
    {
        const float4* gT = (const float4*)(Tin + (size_t)gp * 16);
        #pragma unroll
        for (int i = 0; i < 4; i++) {
            float4 f = gT[i];
            Tm[4*i+0] = f.x; Tm[4*i+1] = f.y; Tm[4*i+2] = f.z; Tm[4*i+3] = f.w;
        }
    }

    float Om[6][6];   // last iteration's Omega (Q[0:6,0:6] + diag(d))

    #pragma unroll 1  // 5 identical GN iterations; keep I$ footprint bounded
    for (int it = 0; it < 5; ++it) {
        const float a0 = Tm[0],  b0 = Tm[1],  c0 = Tm[2],  d0 = Tm[3];
        const float a1 = Tm[4],  b1 = Tm[5],  c1 = Tm[6],  d1 = Tm[7];
        const float a2 = Tm[8],  b2 = Tm[9],  c2 = Tm[10], d2 = Tm[11];

        // sparse dot of P-column i with a 13-vector y
        auto dot0 = [&](const float* y) { return  c0*y[1] - b0*y[2] + c1*y[4] - b1*y[5] + c2*y[7] - b2*y[8]; };
        auto dot1 = [&](const float* y) { return -c0*y[0] + a0*y[2] - c1*y[3] + a1*y[5] - c2*y[6] + a2*y[8]; };
        auto dot2 = [&](const float* y) { return  b0*y[0] - a0*y[1] + b1*y[3] - a1*y[4] + b2*y[6] - a2*y[7]; };
        auto dot3 = [&](const float* y) { return  a0*y[10] + a1*y[11] + a2*y[12]; };
        auto dot4 = [&](const float* y) { return  b0*y[10] + b1*y[11] + b2*y[12]; };
        auto dot5 = [&](const float* y) { return  c0*y[10] + c1*y[11] + c2*y[12]; };

        float Qm[6][6], q[6];
        float y[13];

        // ---- Q = P^T M P, exploiting P sparsity (y_j = M p_j per column) ----
        // col 0
        #pragma unroll
        for (int r = 0; r < 13; r++)
            y[r] = c0*MM(r,1) - b0*MM(r,2) + c1*MM(r,4) - b1*MM(r,5) + c2*MM(r,7) - b2*MM(r,8);
        Qm[0][0] = dot0(y);
        // col 1
        #pragma unroll
        for (int r = 0; r < 13; r++)
            y[r] = -c0*MM(r,0) + a0*MM(r,2) - c1*MM(r,3) + a1*MM(r,5) - c2*MM(r,6) + a2*MM(r,8);
        Qm[0][1] = Qm[1][0] = dot0(y);
        Qm[1][1] = dot1(y);
        // col 2
        #pragma unroll
        for (int r = 0; r < 13; r++)
            y[r] = b0*MM(r,0) - a0*MM(r,1) + b1*MM(r,3) - a1*MM(r,4) + b2*MM(r,6) - a2*MM(r,7);
        Qm[0][2] = Qm[2][0] = dot0(y);
        Qm[1][2] = Qm[2][1] = dot1(y);
        Qm[2][2] = dot2(y);
        // col 3
        #pragma unroll
        for (int r = 0; r < 13; r++)
            y[r] = a0*MM(r,10) + a1*MM(r,11) + a2*MM(r,12);
        Qm[0][3] = Qm[3][0] = dot0(y);
        Qm[1][3] = Qm[3][1] = dot1(y);
        Qm[2][3] = Qm[3][2] = dot2(y);
        Qm[3][3] = dot3(y);
        // col 4
        #pragma unroll
        for (int r = 0; r < 13; r++)
            y[r] = b0*MM(r,10) + b1*MM(r,11) + b2*MM(r,12);
        Qm[0][4] = Qm[4][0] = dot0(y);
        Qm[1][4] = Qm[4][1] = dot1(y);
        Qm[2][4] = Qm[4][2] = dot2(y);
        Qm[3][4] = Qm[4][3] = dot3(y);
        Qm[4][4] = dot4(y);
        // col 5
        #pragma unroll
        for (int r = 0; r < 13; r++)
            y[r] = c0*MM(r,10) + c1*MM(r,11) + c2*MM(r,12);
        Qm[0][5] = Qm[5][0] = dot0(y);
        Qm[1][5] = Qm[5][1] = dot1(y);
        Qm[2][5] = Qm[5][2] = dot2(y);
        Qm[3][5] = Qm[5][3] = dot3(y);
        Qm[4][5] = Qm[5][4] = dot4(y);
        Qm[5][5] = dot5(y);
        // col 6 (dense)
        #pragma unroll
        for (int r = 0; r < 13; r++)
            y[r] = a0*MM(r,0) + b0*MM(r,1) + c0*MM(r,2)
                 + a1*MM(r,3) + b1*MM(r,4) + c1*MM(r,5)
                 + a2*MM(r,6) + b2*MM(r,7) + c2*MM(r,8)
                 + MM(r,9)
                 + d0*MM(r,10) + d1*MM(r,11) + d2*MM(r,12);
        q[0] = dot0(y); q[1] = dot1(y); q[2] = dot2(y);
        q[3] = dot3(y); q[4] = dot4(y); q[5] = dot5(y);

        // ---- regularization (matches reference) ----
        const float regT = 1e-8f * fmaxf(Qm[3][3] + Qm[4][4] + Qm[5][5], 1.0f);
        const float dd[6] = {10.0f, 10.0f, 10.0f, regT, regT, regT};
        #pragma unroll
        for (int i = 0; i < 6; i++) {
            #pragma unroll
            for (int j = 0; j < 6; j++)
                Om[i][j] = Qm[i][j] + ((i == j) ? dd[i] : 0.0f);
        }
        // _inv's reg = 1e-5 * (1 + max(Omega))  (signed max over all entries)
        float mx = Om[0][0];
        #pragma unroll
        for (int i = 0; i < 6; i++) {
            #pragma unroll
            for (int j = 0; j < 6; j++) mx = fmaxf(mx, Om[i][j]);
        }
        const float reg = 1e-5f * (1.0f + mx);

        float A[6][6];
        #pragma unroll
        for (int i = 0; i < 6; i++) {
            #pragma unroll
            for (int j = 0; j < 6; j++)
                A[i][j] = Om[i][j] + ((i == j) ? reg : 0.0f);
        }

        // ---- Cholesky solve A v' = q ; v = -v' ----
        float L[6][6], di[6];
        #pragma unroll
        for (int j = 0; j < 6; j++) {
            float s = A[j][j];
            #pragma unroll
            for (int k = 0; k < j; k++) s -= L[j][k] * L[j][k];
            float ljj = sqrtf(s);
            di[j] = 1.0f / ljj;
            #pragma unroll
            for (int i = j + 1; i < 6; i++) {
                float t = A[i][j];
                #pragma unroll
                for (int k = 0; k < j; k++) t -= L[i][k] * L[j][k];
                L[i][j] = t * di[j];
            }
        }
        float z[6];
        #pragma unroll
        for (int i = 0; i < 6; i++) {
            float s = q[i];
            #pragma unroll
            for (int k = 0; k < i; k++) s -= L[i][k] * z[k];
            z[i] = s * di[i];
        }
        float w[6];
        #pragma unroll
        for (int ii = 5; ii >= 0; ii--) {
            float s = z[ii];
            #pragma unroll
            for (int k = ii + 1; k < 6; k++) s -= L[k][ii] * w[k];
            w[ii] = s * di[ii];
        }

        // v = -w : (omega, rho)
        const float vx = -w[0], vy = -w[1], vz = -w[2];
        const float px = -w[3], py = -w[4], pz = -w[5];

        // ---- closed-form SE(3) exponential (exact, replaces Pade expm) ----
        const float th2 = vx*vx + vy*vy + vz*vz;
        float sA, sB, sC;
        if (th2 > 1e-2f) {
            const float th = sqrtf(th2);
            float sn, cn;
            sincosf(th, &sn, &cn);
            sA = sn / th;
            sB = (1.0f - cn) / th2;
            sC = (1.0f - sA) / th2;
        } else {
            sA = 1.0f - th2 * (1.0f/6.0f)  + th2*th2 * (1.0f/120.0f);
            sB = 0.5f - th2 * (1.0f/24.0f) + th2*th2 * (1.0f/720.0f);
            sC = (1.0f/6.0f) - th2 * (1.0f/120.0f) + th2*th2 * (1.0f/5040.0f);
        }
        const float k00 = -(vy*vy + vz*vz), k11 = -(vx*vx + vz*vz), k22 = -(vx*vx + vy*vy);
        const float kxy = vx*vy, kxz = vx*vz, kyz = vy*vz;

        const float R00 = 1.0f + sB*k00, R01 = -sA*vz + sB*kxy, R02 =  sA*vy + sB*kxz;
        const float R10 =  sA*vz + sB*kxy, R11 = 1.0f + sB*k11, R12 = -sA*vx + sB*kyz;
        const float R20 = -sA*vy + sB*kxz, R21 =  sA*vx + sB*kyz, R22 = 1.0f + sB*k22;

        const float V00 = 1.0f + sC*k00, V01 = -sB*vz + sC*kxy, V02 =  sB*vy + sC*kxz;
        const float V10 =  sB*vz + sC*kxy, V11 = 1.0f + sC*k11, V12 = -sB*vx + sC*kyz;
        const float V20 = -sB*vy + sC*kxz, V21 =  sB*vx + sC*kyz, V22 = 1.0f + sC*k22;

        const float et0 = V00*px + V01*py + V02*pz;
        const float et1 = V10*px + V11*py + V12*pz;
        const float et2 = V20*px + V21*py + V22*pz;

        // ---- T <- T @ expm(hat(v)) ----
        float nT[16];
        #pragma unroll
        for (int i = 0; i < 4; i++) {
            const float r0 = Tm[4*i+0], r1 = Tm[4*i+1], r2 = Tm[4*i+2], r3 = Tm[4*i+3];
            nT[4*i+0] = r0*R00 + r1*R10 + r2*R20;
            nT[4*i+1] = r0*R01 + r1*R11 + r2*R21;
            nT[4*i+2] = r0*R02 + r1*R12 + r2*R22;
            nT[4*i+3] = r0*et0 + r1*et1 + r2*et2 + r3;
        }
        #pragma unroll
        for (int i = 0; i < 16; i++) Tm[i] = nT[i];
    }

    // ---- outputs (float32): T, then Omega / (t_z^2 + 1e-8) ----
    const float tzf = Tm[11];
    const float sc  = 1.0f / (tzf * tzf + 1e-8f);

    // vectorized stores: T as 4x float4
    float4* oT = (float4*)(outT + (size_t)gp * 16);
    #pragma unroll
    for (int i = 0; i < 4; i++)
        oT[i] = make_float4(Tm[4*i+0], Tm[4*i+1], Tm[4*i+2], Tm[4*i+3]);

    float4* oO = (float4*)(outOm + (size_t)gp * 36);
    #pragma unroll
    for (int v4 = 0; v4 < 9; v4++) {
        const int e = v4 * 4;
        oO[v4] = make_float4(Om[(e+0)/6][(e+0)%6] * sc,
                             Om[(e+1)/6][(e+1)%6] * sc,
                             Om[(e+2)/6][(e+2)%6] * sc,
                             Om[(e+3)/6][(e+3)%6] * sc);
    }
}

extern "C" void kernel_launch(void* const* d_in, const int* in_sizes, int n_in,
                              void* d_out, int out_size)
{
    const float* Min = (const float*)d_in[0];   // MTMs [B,C,13,13] fp32
    const float* Tin = (const float*)d_in[1];   // Ts   [B,C,4,4]   fp32
    const int N = in_sizes[0] / 169;

    float* out   = (float*)d_out;
    float* outT  = out;                          // [N,4,4]
    float* outOm = out + (size_t)N * 16;         // [N,6,6]

    const int blocks = (N + NT - 1) / NT;
    mtm_refine_kernel<<<blocks, NT>>>(Min, Tin, outT, outOm, N);
}

// round 3
// speedup vs baseline: 1.2901x; 1.2901x over previous
#include <cuda_runtime.h>
#include <cstdint>

#define NT 128

// packed symmetric index for 13x13 (upper triangle)
__device__ __forceinline__ int sidx(int r, int c) {
    int lo = r < c ? r : c;
    int hi = r < c ? c : r;
    return lo * 13 - (lo * (lo - 1)) / 2 + (hi - lo);
}

#define MM(r, c) sm[sidx((r), (c)) * NT + tid]

// accumulate P[r,I]*w[j] into upper-tri Q (I is a literal)
#define ACC(I, P) do { const float p_ = (P); _Pragma("unroll") \
    for (int j = (I); j < 7; j++) Q[(I)][j] += p_ * w[j]; } while (0)

__global__ void __launch_bounds__(NT, 4)
mtm_refine_kernel(const float* __restrict__ Min, const float* __restrict__ Tin,
                  float* __restrict__ outT, float* __restrict__ outOm, int N)
{
    __shared__ float sm[91 * NT];   // 46592 B: symmetric-packed MtM, [elem][lane]
    const int tid  = threadIdx.x;
    const int base = blockIdx.x * NT;

    // ---- cooperative, coalesced load of MtM into packed-symmetric SMEM ----
    {
        int np = N - base; if (np > NT) np = NT;
        const float* g = Min + (size_t)base * 169;
        const int limit = np * 169;
        for (int idx = tid; idx < limit; idx += NT) {
            int p = idx / 169;
            int e = idx - p * 169;
            int r = e / 13;
            int c = e - r * 13;
            float v = g[idx];
            if (r <= c) sm[sidx(r, c) * NT + p] = v;
        }
    }
    __syncthreads();

    const int gp = base + tid;
    if (gp >= N) return;

    // ---- load T (4x4): rows k -> (ta,tb,tc,td)[k] ----
    float ta[3], tb[3], tc[3], td[3], T3[4]; // T3 = last row (stays [0,0,0,1] but keep general)
    {
        const float4* gT = (const float4*)(Tin + (size_t)gp * 16);
        #pragma unroll
        for (int k = 0; k < 3; k++) {
            float4 f = gT[k];
            ta[k] = f.x; tb[k] = f.y; tc[k] = f.z; td[k] = f.w;
        }
        float4 f = gT[3];
        T3[0] = f.x; T3[1] = f.y; T3[2] = f.z; T3[3] = f.w;
    }

    float OmU[6][6];   // upper-tri Omega of last iteration

    #pragma unroll 1   // 5 identical GN iterations; bound I$ footprint
    for (int it = 0; it < 5; ++it) {
        // Q upper triangle (Q[6][6] unused/never computed)
        float Q[7][7];
        #pragma unroll
        for (int i = 0; i < 7; i++)
            #pragma unroll
            for (int j = i; j < 7; j++) Q[i][j] = 0.0f;

        // ---- single sweep over M rows: each M entry loaded exactly once ----
        #pragma unroll
        for (int r = 0; r < 13; r++) {
            float m[13];
            #pragma unroll
            for (int c = 0; c < 13; c++) m[c] = MM(r, c);

            float w[7];
            w[0] = 0.f; w[1] = 0.f; w[2] = 0.f; w[6] = 0.f;
            #pragma unroll
            for (int k = 0; k < 3; k++) {
                w[0] += tc[k]*m[3*k+1] - tb[k]*m[3*k+2];
                w[1] += ta[k]*m[3*k+2] - tc[k]*m[3*k+0];
                w[2] += tb[k]*m[3*k+0] - ta[k]*m[3*k+1];
                w[6] += ta[k]*m[3*k+0] + tb[k]*m[3*k+1] + tc[k]*m[3*k+2];
            }
            w[3] = ta[0]*m[10] + ta[1]*m[11] + ta[2]*m[12];
            w[4] = tb[0]*m[10] + tb[1]*m[11] + tb[2]*m[12];
            w[5] = tc[0]*m[10] + tc[1]*m[11] + tc[2]*m[12];
            w[6] += m[9] + td[0]*m[10] + td[1]*m[11] + td[2]*m[12];

            // scatter P[r,i]*w into Q (r is compile-time constant after unroll)
            if (r < 9) {
                const int k = r / 3, rr = r - 3 * k;
                if (rr == 0)      { ACC(1, -tc[k]); ACC(2,  tb[k]); }
                else if (rr == 1) { ACC(0,  tc[k]); ACC(2, -ta[k]); }
                else              { ACC(0, -tb[k]); ACC(1,  ta[k]); }
            } else if (r >= 10) {
                const int k = r - 10;
                ACC(3, ta[k]); ACC(4, tb[k]); ACC(5, tc[k]);
            }
            // r == 9: only contributes to Q[6][6] -> skipped
        }

        // ---- regularization (matches reference) ----
        const float regT = 1e-8f * fmaxf(Q[3][3] + Q[4][4] + Q[5][5], 1.0f);
        #pragma unroll
        for (int i = 0; i < 6; i++) {
            const float dd = (i < 3) ? 10.0f : regT;
            #pragma unroll
            for (int j = i; j < 6; j++)
                OmU[i][j] = Q[i][j] + ((i == j) ? dd : 0.0f);
        }
        // _inv's reg = 1e-5 * (1 + max(Omega))  (upper triangle covers all values)
        float mx = OmU[0][0];
        #pragma unroll
        for (int i = 0; i < 6; i++)
            #pragma unroll
            for (int j = i; j < 6; j++) mx = fmaxf(mx, OmU[i][j]);
        const float reg = 1e-5f * (1.0f + mx);

        float A[6][6];   // upper-tri only
        #pragma unroll
        for (int i = 0; i < 6; i++)
            #pragma unroll
            for (int j = i; j < 6; j++)
                A[i][j] = OmU[i][j] + ((i == j) ? reg : 0.0f);

        // ---- Cholesky solve A v' = q ; v = -v' ----
        float L[6][6], di[6];
        #pragma unroll
        for (int j = 0; j < 6; j++) {
            float s = A[j][j];
            #pragma unroll
            for (int k = 0; k < j; k++) s -= L[j][k] * L[j][k];
            di[j] = rsqrtf(s);
            #pragma unroll
            for (int i = j + 1; i < 6; i++) {
                float t = A[j][i];          // A[i][j] with i>j -> upper mirror
                #pragma unroll
                for (int k = 0; k < j; k++) t -= L[i][k] * L[j][k];
                L[i][j] = t * di[j];
            }
        }
        float z[6];
        #pragma unroll
        for (int i = 0; i < 6; i++) {
            float s = Q[i][6];              // q[i]
            #pragma unroll
            for (int k = 0; k < i; k++) s -= L[i][k] * z[k];
            z[i] = s * di[i];
        }
        float w6v[6];
        #pragma unroll
        for (int ii = 5; ii >= 0; ii--) {
            float s = z[ii];
            #pragma unroll
            for (int k = ii + 1; k < 6; k++) s -= L[k][ii] * w6v[k];
            w6v[ii] = s * di[ii];
        }

        const float vx = -w6v[0], vy = -w6v[1], vz = -w6v[2];
        const float px = -w6v[3], py = -w6v[4], pz = -w6v[5];

        // ---- closed-form SE(3) exponential ----
        const float th2 = vx*vx + vy*vy + vz*vz;
        float sA, sB, sC;
        if (th2 > 1e-2f) {
            const float th = sqrtf(th2);
            float sn, cn;
            __sincosf(th, &sn, &cn);
            sA = sn / th;
            sB = (1.0f - cn) / th2;
            sC = (1.0f - sA) / th2;
        } else {
            sA = 1.0f - th2 * (1.0f/6.0f)  + th2*th2 * (1.0f/120.0f);
            sB = 0.5f - th2 * (1.0f/24.0f) + th2*th2 * (1.0f/720.0f);
            sC = (1.0f/6.0f) - th2 * (1.0f/120.0f) + th2*th2 * (1.0f/5040.0f);
        }
        const float k00 = -(vy*vy + vz*vz), k11 = -(vx*vx + vz*vz), k22 = -(vx*vx + vy*vy);
        const float kxy = vx*vy, kxz = vx*vz, kyz = vy*vz;

        const float R00 = 1.0f + sB*k00, R01 = -sA*vz + sB*kxy, R02 =  sA*vy + sB*kxz;
        const float R10 =  sA*vz + sB*kxy, R11 = 1.0f + sB*k11, R12 = -sA*vx + sB*kyz;
        const float R20 = -sA*vy + sB*kxz, R21 =  sA*vx + sB*kyz, R22 = 1.0f + sB*k22;

        const float V00 = 1.0f + sC*k00, V01 = -sB*vz + sC*kxy, V02 =  sB*vy + sC*kxz;
        const float V10 =  sB*vz + sC*kxy, V11 = 1.0f + sC*k11, V12 = -sB*vx + sC*kyz;
        const float V20 = -sB*vy + sC*kxz, V21 =  sB*vx + sC*kyz, V22 = 1.0f + sC*k22;

        const float et0 = V00*px + V01*py + V02*pz;
        const float et1 = V10*px + V11*py + V12*pz;
        const float et2 = V20*px + V21*py + V22*pz;

        // ---- T <- T @ expm(hat(v)) (rows 0..2; row 3 unchanged) ----
        #pragma unroll
        for (int k = 0; k < 3; k++) {
            const float r0 = ta[k], r1 = tb[k], r2 = tc[k], r3 = td[k];
            ta[k] = r0*R00 + r1*R10 + r2*R20;
            tb[k] = r0*R01 + r1*R11 + r2*R21;
            tc[k] = r0*R02 + r1*R12 + r2*R22;
            td[k] = r0*et0 + r1*et1 + r2*et2 + r3;
        }
    }

    // ---- outputs (float32): T, then Omega / (t_z^2 + 1e-8) ----
    const float tzf = td[2];
    const float sc  = 1.0f / (tzf * tzf + 1e-8f);

    float4* oT = (float4*)(outT + (size_t)gp * 16);
    #pragma unroll
    for (int k = 0; k < 3; k++)
        oT[k] = make_float4(ta[k], tb[k], tc[k], td[k]);
    oT[3] = make_float4(T3[0], T3[1], T3[2], T3[3]);

    // full symmetric Omega scaled
    float Of[36];
    #pragma unroll
    for (int i = 0; i < 6; i++)
        #pragma unroll
        for (int j = 0; j < 6; j++)
            Of[i*6 + j] = ((i <= j) ? OmU[i][j] : OmU[j][i]) * sc;

    float4* oO = (float4*)(outOm + (size_t)gp * 36);
    #pragma unroll
    for (int v4 = 0; v4 < 9; v4++)
        oO[v4] = make_float4(Of[v4*4+0], Of[v4*4+1], Of[v4*4+2], Of[v4*4+3]);
}

extern "C" void kernel_launch(void* const* d_in, const int* in_sizes, int n_in,
                              void* d_out, int out_size)
{
    const float* Min = (const float*)d_in[0];   // MTMs [B,C,13,13] fp32
    const float* Tin = (const float*)d_in[1];   // Ts   [B,C,4,4]   fp32
    const int N = in_sizes[0] / 169;

    float* out   = (float*)d_out;
    float* outT  = out;                          // [N,4,4]
    float* outOm = out + (size_t)N * 16;         // [N,6,6]

    const int blocks = (N + NT - 1) / NT;
    mtm_refine_kernel<<<blocks, NT>>>(Min, Tin, outT, outOm, N);
}

// round 4
// speedup vs baseline: 1.3938x; 1.0804x over previous
#include <cuda_runtime.h>
#include <cstdint>

#define NT 128
#define SMS 129   // skewed stride: (s*129 + p) % 32 = (s+p) % 32 -> conflict-free both phases

// packed symmetric index for 13x13 (upper triangle), compile-time after unroll
__device__ __forceinline__ int sidx(int r, int c) {
    int lo = r < c ? r : c;
    int hi = r < c ? c : r;
    return lo * 13 - (lo * (lo - 1)) / 2 + (hi - lo);
}

#define MM(r, c) sm[sidx((r), (c)) * SMS + tid]

// accumulate P[r,I]*w[j] into upper-tri Q (I is a literal)
#define ACC(I, P) do { const float p_ = (P); _Pragma("unroll") \
    for (int j = (I); j < 7; j++) Q[(I)][j] += p_ * w[j]; } while (0)

__global__ void __launch_bounds__(NT, 4)
mtm_refine_kernel(const float* __restrict__ Min, const float* __restrict__ Tin,
                  float* __restrict__ outT, float* __restrict__ outOm, int N)
{
    __shared__ float sm[91 * SMS];   // 46956 B
    const int tid  = threadIdx.x;
    const int base = blockIdx.x * NT;

    // ---- cooperative, coalesced fill: no divides, no 32-way STS conflicts ----
    {
        int np = N - base; if (np > NT) np = NT;
        const float* g = Min + (size_t)base * 169;
        const int limit = np * 169;
        // idx = p*169 + e ; e = 13*r + c. tid < 169 so initial p=0, e=tid.
        int p = 0, r = tid / 13, c = tid % 13;   // one-time small divides
        for (int idx = tid; idx < limit; idx += NT) {
            const int lo = r < c ? r : c;
            const int hi = r < c ? c : r;
            const int s  = lo * 13 - ((lo * (lo - 1)) >> 1) + (hi - lo);
            sm[s * SMS + p] = g[idx];
            // advance e by 128 = 9*13 + 11
            r += 9; c += 11;
            if (c >= 13) { c -= 13; r += 1; }
            if (r >= 13) { r -= 13; p += 1; }   // e wrapped past 169
        }
    }
    __syncthreads();

    const int gp = base + tid;
    if (gp >= N) return;

    // ---- load T (4x4): rows k -> (ta,tb,tc,td)[k] ----
    float ta[3], tb[3], tc[3], td[3], T3[4];
    {
        const float4* gT = (const float4*)(Tin + (size_t)gp * 16);
        #pragma unroll
        for (int k = 0; k < 3; k++) {
            float4 f = gT[k];
            ta[k] = f.x; tb[k] = f.y; tc[k] = f.z; td[k] = f.w;
        }
        float4 f = gT[3];
        T3[0] = f.x; T3[1] = f.y; T3[2] = f.z; T3[3] = f.w;
    }

    float OmU[6][6];   // upper-tri Omega of last iteration

    #pragma unroll 1   // 5 identical GN iterations; bound I$ footprint
    for (int it = 0; it < 5; ++it) {
        float Q[7][7];
        #pragma unroll
        for (int i = 0; i < 7; i++)
            #pragma unroll
            for (int j = i; j < 7; j++) Q[i][j] = 0.0f;

        // ---- single sweep over M rows (row 9 contributes only to unused Q[6][6]) ----
        #pragma unroll
        for (int r = 0; r < 13; r++) {
            if (r == 9) continue;
            float m[13];
            #pragma unroll
            for (int c = 0; c < 13; c++) m[c] = MM(r, c);

            float w[7];
            w[0] = 0.f; w[1] = 0.f; w[2] = 0.f; w[6] = 0.f;
            #pragma unroll
            for (int k = 0; k < 3; k++) {
                w[0] += tc[k]*m[3*k+1] - tb[k]*m[3*k+2];
                w[1] += ta[k]*m[3*k+2] - tc[k]*m[3*k+0];
                w[2] += tb[k]*m[3*k+0] - ta[k]*m[3*k+1];
                w[6] += ta[k]*m[3*k+0] + tb[k]*m[3*k+1] + tc[k]*m[3*k+2];
            }
            w[3] = ta[0]*m[10] + ta[1]*m[11] + ta[2]*m[12];
            w[4] = tb[0]*m[10] + tb[1]*m[11] + tb[2]*m[12];
            w[5] = tc[0]*m[10] + tc[1]*m[11] + tc[2]*m[12];
            w[6] += m[9] + td[0]*m[10] + td[1]*m[11] + td[2]*m[12];

            if (r < 9) {
                const int k = r / 3, rr = r - 3 * k;
                if (rr == 0)      { ACC(1, -tc[k]); ACC(2,  tb[k]); }
                else if (rr == 1) { ACC(0,  tc[k]); ACC(2, -ta[k]); }
                else              { ACC(0, -tb[k]); ACC(1,  ta[k]); }
            } else {
                const int k = r - 10;
                ACC(3, ta[k]); ACC(4, tb[k]); ACC(5, tc[k]);
            }
        }

        // ---- regularization (matches reference) ----
        const float regT = 1e-8f * fmaxf(Q[3][3] + Q[4][4] + Q[5][5], 1.0f);
        #pragma unroll
        for (int i = 0; i < 6; i++) {
            const float dd = (i < 3) ? 10.0f : regT;
            #pragma unroll
            for (int j = i; j < 6; j++)
                OmU[i][j] = Q[i][j] + ((i == j) ? dd : 0.0f);
        }
        float mx = OmU[0][0];
        #pragma unroll
        for (int i = 0; i < 6; i++)
            #pragma unroll
            for (int j = i; j < 6; j++) mx = fmaxf(mx, OmU[i][j]);
        const float reg = 1e-5f * (1.0f + mx);

        float A[6][6];   // upper-tri only
        #pragma unroll
        for (int i = 0; i < 6; i++)
            #pragma unroll
            for (int j = i; j < 6; j++)
                A[i][j] = OmU[i][j] + ((i == j) ? reg : 0.0f);

        // ---- Cholesky solve A v' = q ; v = -v' ----
        float L[6][6], di[6];
        #pragma unroll
        for (int j = 0; j < 6; j++) {
            float s = A[j][j];
            #pragma unroll
            for (int k = 0; k < j; k++) s -= L[j][k] * L[j][k];
            di[j] = rsqrtf(s);
            #pragma unroll
            for (int i = j + 1; i < 6; i++) {
                float t = A[j][i];
                #pragma unroll
                for (int k = 0; k < j; k++) t -= L[i][k] * L[j][k];
                L[i][j] = t * di[j];
            }
        }
        float z[6];
        #pragma unroll
        for (int i = 0; i < 6; i++) {
            float s = Q[i][6];              // q[i]
            #pragma unroll
            for (int k = 0; k < i; k++) s -= L[i][k] * z[k];
            z[i] = s * di[i];
        }
        float w6v[6];
        #pragma unroll
        for (int ii = 5; ii >= 0; ii--) {
            float s = z[ii];
            #pragma unroll
            for (int k = ii + 1; k < 6; k++) s -= L[k][ii] * w6v[k];
            w6v[ii] = s * di[ii];
        }

        const float vx = -w6v[0], vy = -w6v[1], vz = -w6v[2];
        const float px = -w6v[3], py = -w6v[4], pz = -w6v[5];

        // ---- closed-form SE(3) exponential ----
        const float th2 = vx*vx + vy*vy + vz*vz;
        float sA, sB, sC;
        if (th2 > 1e-2f) {
            const float th = sqrtf(th2);
            float sn, cn;
            __sincosf(th, &sn, &cn);
            sA = sn / th;
            sB = (1.0f - cn) / th2;
            sC = (1.0f - sA) / th2;
        } else {
            sA = 1.0f - th2 * (1.0f/6.0f)  + th2*th2 * (1.0f/120.0f);
            sB = 0.5f - th2 * (1.0f/24.0f) + th2*th2 * (1.0f/720.0f);
            sC = (1.0f/6.0f) - th2 * (1.0f/120.0f) + th2*th2 * (1.0f/5040.0f);
        }
        const float k00 = -(vy*vy + vz*vz), k11 = -(vx*vx + vz*vz), k22 = -(vx*vx + vy*vy);
        const float kxy = vx*vy, kxz = vx*vz, kyz = vy*vz;

        const float R00 = 1.0f + sB*k00, R01 = -sA*vz + sB*kxy, R02 =  sA*vy + sB*kxz;
        const float R10 =  sA*vz + sB*kxy, R11 = 1.0f + sB*k11, R12 = -sA*vx + sB*kyz;
        const float R20 = -sA*vy + sB*kxz, R21 =  sA*vx + sB*kyz, R22 = 1.0f + sB*k22;

        const float V00 = 1.0f + sC*k00, V01 = -sB*vz + sC*kxy, V02 =  sB*vy + sC*kxz;
        const float V10 =  sB*vz + sC*kxy, V11 = 1.0f + sC*k11, V12 = -sB*vx + sC*kyz;
        const float V20 = -sB*vy + sC*kxz, V21 =  sB*vx + sC*kyz, V22 = 1.0f + sC*k22;

        const float et0 = V00*px + V01*py + V02*pz;
        const float et1 = V10*px + V11*py + V12*pz;
        const float et2 = V20*px + V21*py + V22*pz;

        // ---- T <- T @ expm(hat(v)) (rows 0..2; row 3 unchanged) ----
        #pragma unroll
        for (int k = 0; k < 3; k++) {
            const float r0 = ta[k], r1 = tb[k], r2 = tc[k], r3 = td[k];
            ta[k] = r0*R00 + r1*R10 + r2*R20;
            tb[k] = r0*R01 + r1*R11 + r2*R21;
            tc[k] = r0*R02 + r1*R12 + r2*R22;
            td[k] = r0*et0 + r1*et1 + r2*et2 + r3;
        }
    }

    // ---- outputs (float32): T, then Omega / (t_z^2 + 1e-8) ----
    const float tzf = td[2];
    const float sc  = 1.0f / (tzf * tzf + 1e-8f);

    float4* oT = (float4*)(outT + (size_t)gp * 16);
    #pragma unroll
    for (int k = 0; k < 3; k++)
        oT[k] = make_float4(ta[k], tb[k], tc[k], td[k]);
    oT[3] = make_float4(T3[0], T3[1], T3[2], T3[3]);

    float Of[36];
    #pragma unroll
    for (int i = 0; i < 6; i++)
        #pragma unroll
        for (int j = 0; j < 6; j++)
            Of[i*6 + j] = ((i <= j) ? OmU[i][j] : OmU[j][i]) * sc;

    float4* oO = (float4*)(outOm + (size_t)gp * 36);
    #pragma unroll
    for (int v4 = 0; v4 < 9; v4++)
        oO[v4] = make_float4(Of[v4*4+0], Of[v4*4+1], Of[v4*4+2], Of[v4*4+3]);
}

extern "C" void kernel_launch(void* const* d_in, const int* in_sizes, int n_in,
                              void* d_out, int out_size)
{
    const float* Min = (const float*)d_in[0];   // MTMs [B,C,13,13] fp32
    const float* Tin = (const float*)d_in[1];   // Ts   [B,C,4,4]   fp32
    const int N = in_sizes[0] / 169;

    float* out   = (float*)d_out;
    float* outT  = out;                          // [N,4,4]
    float* outOm = out + (size_t)N * 16;         // [N,6,6]

    const int blocks = (N + NT - 1) / NT;
    mtm_refine_kernel<<<blocks, NT>>>(Min, Tin, outT, outOm, N);
}

// round 5
// speedup vs baseline: 1.4979x; 1.0747x over previous
#include <cuda_runtime.h>
#include <cstdint>

#define NT  64
#define SMS 65   // (s*65 + p) % 32 = (s + p) % 32 -> conflict-free fill & compute

// packed symmetric index for 13x13 (upper triangle), compile-time after unroll
__device__ __forceinline__ int sidx(int r, int c) {
    int lo = r < c ? r : c;
    int hi = r < c ? c : r;
    return lo * 13 - (lo * (lo - 1)) / 2 + (hi - lo);
}

#define MM(r, c) sm[sidx((r), (c)) * SMS + tid]

// accumulate P[r,I]*w[j] into upper-tri Q (I is a literal)
#define ACC(I, P) do { const float p_ = (P); _Pragma("unroll") \
    for (int j = (I); j < 7; j++) Q[(I)][j] += p_ * w[j]; } while (0)

__global__ void __launch_bounds__(NT, 9)
mtm_refine_kernel(const float* __restrict__ Min, const float* __restrict__ Tin,
                  float* __restrict__ outT, float* __restrict__ outOm, int N)
{
    __shared__ float sm[91 * SMS];            // 23,660 B
    __shared__ unsigned short lut[169];       // packed offset s*SMS per element index

    const int tid  = threadIdx.x;
    const int base = blockIdx.x * NT;

    // ---- build element->packed-slot LUT ----
    for (int e = tid; e < 169; e += NT) {
        const int r = e / 13, c = e - (e / 13) * 13;
        const int lo = r < c ? r : c;
        const int hi = r < c ? c : r;
        lut[e] = (unsigned short)((lo * 13 - ((lo * (lo - 1)) >> 1) + (hi - lo)) * SMS);
    }
    __syncthreads();

    // ---- vectorized cooperative fill (float4 LDG + LUT STS) ----
    {
        int np = N - base; if (np > NT) np = NT;
        const int limit  = np * 169;
        const int limit4 = limit >> 2;
        const float4* g4 = (const float4*)(Min + (size_t)base * 169);

        // chunk i4 covers elements e_glob = 4*i4 .. 4*i4+3 ; p = e_glob/169
        int p = 0, e = 4 * tid;
        if (e >= 169) { e -= 169; p++; }     // 4*tid <= 252 < 338
        for (int i4 = tid; i4 < limit4; i4 += NT) {
            const float4 v = g4[i4];
            int ek = e, pk = p;
            float vv0 = v.x, vv1 = v.y, vv2 = v.z, vv3 = v.w;
            if (ek >= 169) { ek -= 169; pk++; } sm[(int)lut[ek] + pk] = vv0; ek++;
            if (ek >= 169) { ek -= 169; pk++; } sm[(int)lut[ek] + pk] = vv1; ek++;
            if (ek >= 169) { ek -= 169; pk++; } sm[(int)lut[ek] + pk] = vv2; ek++;
            if (ek >= 169) { ek -= 169; pk++; } sm[(int)lut[ek] + pk] = vv3;
            // advance by 4*NT = 256 = 169 + 87
            e += 87; p += 1;
            if (e >= 169) { e -= 169; p += 1; }
        }
        // scalar tail (only when np*169 % 4 != 0, i.e. partial last block)
        for (int idx = limit4 * 4 + tid; idx < limit; idx += NT) {
            const int pp = idx / 169;
            sm[(int)lut[idx - pp * 169] + pp] = Min[(size_t)base * 169 + idx];
        }
    }
    __syncthreads();

    const int gp = base + tid;
    if (gp >= N) return;

    // ---- load T rows 0..2: (ta,tb,tc,td)[k] ----
    float ta[3], tb[3], tc[3], td[3];
    {
        const float4* gT = (const float4*)(Tin + (size_t)gp * 16);
        #pragma unroll
        for (int k = 0; k < 3; k++) {
            float4 f = gT[k];
            ta[k] = f.x; tb[k] = f.y; tc[k] = f.z; td[k] = f.w;
        }
    }

    float OmU[6][6];   // upper-tri Omega of last iteration

    #pragma unroll 1   // 5 identical GN iterations; bound I$ footprint
    for (int it = 0; it < 5; ++it) {
        float Q[7][7];
        #pragma unroll
        for (int i = 0; i < 7; i++)
            #pragma unroll
            for (int j = i; j < 7; j++) Q[i][j] = 0.0f;

        // ---- single sweep over M rows (row 9 only feeds unused Q[6][6]) ----
        #pragma unroll
        for (int r = 0; r < 13; r++) {
            if (r == 9) continue;
            float m[13];
            #pragma unroll
            for (int c = 0; c < 13; c++) m[c] = MM(r, c);

            float w[7];
            w[0] = 0.f; w[1] = 0.f; w[2] = 0.f; w[6] = 0.f;
            #pragma unroll
            for (int k = 0; k < 3; k++) {
                w[0] += tc[k]*m[3*k+1] - tb[k]*m[3*k+2];
                w[1] += ta[k]*m[3*k+2] - tc[k]*m[3*k+0];
                w[2] += tb[k]*m[3*k+0] - ta[k]*m[3*k+1];
                w[6] += ta[k]*m[3*k+0] + tb[k]*m[3*k+1] + tc[k]*m[3*k+2];
            }
            w[3] = ta[0]*m[10] + ta[1]*m[11] + ta[2]*m[12];
            w[4] = tb[0]*m[10] + tb[1]*m[11] + tb[2]*m[12];
            w[5] = tc[0]*m[10] + tc[1]*m[11] + tc[2]*m[12];
            w[6] += m[9] + td[0]*m[10] + td[1]*m[11] + td[2]*m[12];

            if (r < 9) {
                const int k = r / 3, rr = r - 3 * k;
                if (rr == 0)      { ACC(1, -tc[k]); ACC(2,  tb[k]); }
                else if (rr == 1) { ACC(0,  tc[k]); ACC(2, -ta[k]); }
                else              { ACC(0, -tb[k]); ACC(1,  ta[k]); }
            } else {
                const int k = r - 10;
                ACC(3, ta[k]); ACC(4, tb[k]); ACC(5, tc[k]);
            }
        }

        // ---- regularization (matches reference) ----
        const float regT = 1e-8f * fmaxf(Q[3][3] + Q[4][4] + Q[5][5], 1.0f);
        #pragma unroll
        for (int i = 0; i < 6; i++) {
            const float dd = (i < 3) ? 10.0f : regT;
            #pragma unroll
            for (int j = i; j < 6; j++)
                OmU[i][j] = Q[i][j] + ((i == j) ? dd : 0.0f);
        }
        float mx = OmU[0][0];
        #pragma unroll
        for (int i = 0; i < 6; i++)
            #pragma unroll
            for (int j = i; j < 6; j++) mx = fmaxf(mx, OmU[i][j]);
        const float reg = 1e-5f * (1.0f + mx);

        float A[6][6];   // upper-tri only
        #pragma unroll
        for (int i = 0; i < 6; i++)
            #pragma unroll
            for (int j = i; j < 6; j++)
                A[i][j] = OmU[i][j] + ((i == j) ? reg : 0.0f);

        // ---- Cholesky solve A v' = q ; v = -v' ----
        float L[6][6], di[6];
        #pragma unroll
        for (int j = 0; j < 6; j++) {
            float s = A[j][j];
            #pragma unroll
            for (int k = 0; k < j; k++) s -= L[j][k] * L[j][k];
            di[j] = rsqrtf(s);
            #pragma unroll
            for (int i = j + 1; i < 6; i++) {
                float t = A[j][i];
                #pragma unroll
                for (int k = 0; k < j; k++) t -= L[i][k] * L[j][k];
                L[i][j] = t * di[j];
            }
        }
        float z[6];
        #pragma unroll
        for (int i = 0; i < 6; i++) {
            float s = Q[i][6];              // q[i]
            #pragma unroll
            for (int k = 0; k < i; k++) s -= L[i][k] * z[k];
            z[i] = s * di[i];
        }
        float w6v[6];
        #pragma unroll
        for (int ii = 5; ii >= 0; ii--) {
            float s = z[ii];
            #pragma unroll
            for (int k = ii + 1; k < 6; k++) s -= L[k][ii] * w6v[k];
            w6v[ii] = s * di[ii];
        }

        const float vx = -w6v[0], vy = -w6v[1], vz = -w6v[2];
        const float px = -w6v[3], py = -w6v[4], pz = -w6v[5];

        // ---- closed-form SE(3) exponential ----
        const float th2 = vx*vx + vy*vy + vz*vz;
        float sA, sB, sC;
        if (th2 > 1e-2f) {
            const float th = sqrtf(th2);
            float sn, cn;
            __sincosf(th, &sn, &cn);
            sA = sn / th;
            sB = (1.0f - cn) / th2;
            sC = (1.0f - sA) / th2;
        } else {
            sA = 1.0f - th2 * (1.0f/6.0f)  + th2*th2 * (1.0f/120.0f);
            sB = 0.5f - th2 * (1.0f/24.0f) + th2*th2 * (1.0f/720.0f);
            sC = (1.0f/6.0f) - th2 * (1.0f/120.0f) + th2*th2 * (1.0f/5040.0f);
        }
        const float k00 = -(vy*vy + vz*vz), k11 = -(vx*vx + vz*vz), k22 = -(vx*vx + vy*vy);
        const float kxy = vx*vy, kxz = vx*vz, kyz = vy*vz;

        const float R00 = 1.0f + sB*k00, R01 = -sA*vz + sB*kxy, R02 =  sA*vy + sB*kxz;
        const float R10 =  sA*vz + sB*kxy, R11 = 1.0f + sB*k11, R12 = -sA*vx + sB*kyz;
        const float R20 = -sA*vy + sB*kxz, R21 =  sA*vx + sB*kyz, R22 = 1.0f + sB*k22;

        const float V00 = 1.0f + sC*k00, V01 = -sB*vz + sC*kxy, V02 =  sB*vy + sC*kxz;
        const float V10 =  sB*vz + sC*kxy, V11 = 1.0f + sC*k11, V12 = -sB*vx + sC*kyz;
        const float V20 = -sB*vy + sC*kxz, V21 =  sB*vx + sC*kyz, V22 = 1.0f + sC*k22;

        const float et0 = V00*px + V01*py + V02*pz;
        const float et1 = V10*px + V11*py + V12*pz;
        const float et2 = V20*px + V21*py + V22*pz;

        // ---- T <- T @ expm(hat(v)) (rows 0..2; row 3 unchanged) ----
        #pragma unroll
        for (int k = 0; k < 3; k++) {
            const float r0 = ta[k], r1 = tb[k], r2 = tc[k], r3 = td[k];
            ta[k] = r0*R00 + r1*R10 + r2*R20;
            tb[k] = r0*R01 + r1*R11 + r2*R21;
            tc[k] = r0*R02 + r1*R12 + r2*R22;
            td[k] = r0*et0 + r1*et1 + r2*et2 + r3;
        }
    }

    // ---- outputs (float32): T, then Omega / (t_z^2 + 1e-8) ----
    const float tzf = td[2];
    const float sc  = 1.0f / (tzf * tzf + 1e-8f);

    float4* oT = (float4*)(outT + (size_t)gp * 16);
    #pragma unroll
    for (int k = 0; k < 3; k++)
        oT[k] = make_float4(ta[k], tb[k], tc[k], td[k]);
    // last row of T is unchanged by boxplus (expm row3 = [0,0,0,1]): pass through input
    oT[3] = ((const float4*)(Tin + (size_t)gp * 16))[3];

    float Of[36];
    #pragma unroll
    for (int i = 0; i < 6; i++)
        #pragma unroll
        for (int j = 0; j < 6; j++)
            Of[i*6 + j] = ((i <= j) ? OmU[i][j] : OmU[j][i]) * sc;

    float4* oO = (float4*)(outOm + (size_t)gp * 36);
    #pragma unroll
    for (int v4 = 0; v4 < 9; v4++)
        oO[v4] = make_float4(Of[v4*4+0], Of[v4*4+1], Of[v4*4+2], Of[v4*4+3]);
}

extern "C" void kernel_launch(void* const* d_in, const int* in_sizes, int n_in,
                              void* d_out, int out_size)
{
    const float* Min = (const float*)d_in[0];   // MTMs [B,C,13,13] fp32
    const float* Tin = (const float*)d_in[1];   // Ts   [B,C,4,4]   fp32
    const int N = in_sizes[0] / 169;

    float* out   = (float*)d_out;
    float* outT  = out;                          // [N,4,4]
    float* outOm = out + (size_t)N * 16;         // [N,6,6]

    const int blocks = (N + NT - 1) / NT;
    mtm_refine_kernel<<<blocks, NT>>>(Min, Tin, outT, outOm, N);
}